// round 15
// baseline (speedup 1.0000x reference)
#include <cuda_runtime.h>
#include <cstdint>

// NodePropagatorSparse: out[b,e,0:256]   = node_states[b, edge_src[e], :]
//                       out[b,e,256:512] = node_states[b, edge_tgt[e], :]
// B=4, N=10000, E=160000, D=256. node_states fp32, indices int32 (JAX x64-off).
//
// R14 (= R12 resubmit; prior round was an infra failure, no measurement):
// batch phasing via blockIdx.y (per-phase gather set = 10.24MB, L2-resident
// -> DRAM traffic at the 1.36GB floor), edge-unroll x4 (MLP=4 saturates the
// write drain; x8 measured neutral), float4 128-bit ops (256-bit measured
// regression), __stcs evict-first streaming stores, 32-bit offset arithmetic.
// 512-thread CTAs: 16KB contiguous writes per CTA for DRAM page-hit
// friendliness.

#define B_DIM 4
#define N_DIM 10000
#define E_DIM 160000
#define D_DIM 256
#define D4    (D_DIM / 4)        // 64 float4 per D-row
#define ROW4  (2 * D4)           // 128 float4 per output (b,e) row
#define EDGES_PER_BLOCK 16
#define UNROLL 4

__global__ __launch_bounds__(512, 4)
void node_prop_gather_kernel(const float4* __restrict__ ns4,   // [B, N, D4]
                             const int* __restrict__ src,      // [E] int32
                             const int* __restrict__ tgt,      // [E] int32
                             float4* __restrict__ out4)        // [B, E, ROW4]
{
    const int t    = threadIdx.x;                 // 0..511
    const int b    = blockIdx.y;                  // batch phase
    const int half = (t >> 6) & 1;                // 0 = src half, 1 = tgt half
    const int col  = t & 63;                      // float4 column within D-row
    const int esub = t >> 7;                      // 0..3: edge-within-group

    const int e0 = blockIdx.x * EDGES_PER_BLOCK + esub;
    const int* iarr = half ? tgt : src;

    // 32-bit offsets: max out offset = 4*160000*128 = 81.92M float4 (fits int)
    const float4* nsb  = ns4  + (b * N_DIM) * D4 + col;
    float4*       outb = out4 + (b * E_DIM + e0) * ROW4 + half * D4 + col;

    int idx[UNROLL];
#pragma unroll
    for (int u = 0; u < UNROLL; u++)
        idx[u] = __ldg(&iarr[e0 + 4 * u]);

    float4 v[UNROLL];
#pragma unroll
    for (int u = 0; u < UNROLL; u++)
        v[u] = nsb[idx[u] * D4];

#pragma unroll
    for (int u = 0; u < UNROLL; u++)
        __stcs(outb + (4 * u) * ROW4, v[u]);
}

extern "C" void kernel_launch(void* const* d_in, const int* in_sizes, int n_in,
                              void* d_out, int out_size)
{
    const float4* ns4  = (const float4*)d_in[0];
    const int*    src  = (const int*)d_in[1];
    const int*    tgt  = (const int*)d_in[2];
    float4*       out4 = (float4*)d_out;

    dim3 grid(E_DIM / EDGES_PER_BLOCK, B_DIM);   // (10000, 4)
    node_prop_gather_kernel<<<grid, 512>>>(ns4, src, tgt, out4);
}

// round 16
// speedup vs baseline: 1.0028x; 1.0028x over previous
#include <cuda_runtime.h>
#include <cstdint>

// NodePropagatorSparse: out[b,e,0:256]   = node_states[b, edge_src[e], :]
//                       out[b,e,256:512] = node_states[b, edge_tgt[e], :]
// B=4, N=10000, E=160000, D=256. node_states fp32, indices int32 (JAX x64-off).
//
// FINAL (R11 config, best measured 184.8us @ DRAM 88%, traffic at the
// 1.36GB mandatory floor):
//  - batch phasing via blockIdx.y: per-phase gather set = 10.24MB, fully
//    L2-resident -> zero excess DRAM reads (removed 0.36GB vs naive).
//  - edge-unroll x4 (MLP=4): saturates the DRAM write drain; x8 measured
//    neutral, x1 measured issue-limited.
//  - float4 128-bit LDG/STG: 256-bit .v8 path measured as a regression on
//    sm_103 gathers; evict_last hint measured as a regression (L2 carve-out
//    thrash).
//  - __stcs evict-first streaming stores: protects the gather working set.
//  - 32-bit offset arithmetic throughout.

#define B_DIM 4
#define N_DIM 10000
#define E_DIM 160000
#define D_DIM 256
#define D4    (D_DIM / 4)        // 64 float4 per D-row
#define ROW4  (2 * D4)           // 128 float4 per output (b,e) row
#define EDGES_PER_BLOCK 8
#define UNROLL 4

__global__ __launch_bounds__(256, 8)
void node_prop_gather_kernel(const float4* __restrict__ ns4,   // [B, N, D4]
                             const int* __restrict__ src,      // [E] int32
                             const int* __restrict__ tgt,      // [E] int32
                             float4* __restrict__ out4)        // [B, E, ROW4]
{
    const int t    = threadIdx.x;                 // 0..255
    const int b    = blockIdx.y;                  // batch phase
    const int half = (t >> 6) & 1;                // 0 = src half, 1 = tgt half
    const int col  = t & 63;                      // float4 column within D-row
    const int esub = t >> 7;                      // 0..1: edge-within-pair

    const int e0 = blockIdx.x * EDGES_PER_BLOCK + esub;
    const int* iarr = half ? tgt : src;

    // 32-bit offsets: max out offset = 4*160000*128 = 81.92M float4 (fits int)
    const float4* nsb  = ns4  + (b * N_DIM) * D4 + col;
    float4*       outb = out4 + (b * E_DIM + e0) * ROW4 + half * D4 + col;

    int idx[UNROLL];
#pragma unroll
    for (int u = 0; u < UNROLL; u++)
        idx[u] = __ldg(&iarr[e0 + 2 * u]);

    float4 v[UNROLL];
#pragma unroll
    for (int u = 0; u < UNROLL; u++)
        v[u] = nsb[idx[u] * D4];

#pragma unroll
    for (int u = 0; u < UNROLL; u++)
        __stcs(outb + (2 * u) * ROW4, v[u]);
}

extern "C" void kernel_launch(void* const* d_in, const int* in_sizes, int n_in,
                              void* d_out, int out_size)
{
    const float4* ns4  = (const float4*)d_in[0];
    const int*    src  = (const int*)d_in[1];
    const int*    tgt  = (const int*)d_in[2];
    float4*       out4 = (float4*)d_out;

    dim3 grid(E_DIM / EDGES_PER_BLOCK, B_DIM);   // (20000, 4)
    node_prop_gather_kernel<<<grid, 256>>>(ns4, src, tgt, out4);
}